// round 13
// baseline (speedup 1.0000x reference)
#include <cuda_runtime.h>

#define DATA_DIM 512
#define BASIS_DIM 64
#define N_ROWS 2048
#define N_SPANS 61
#define THREADS 128

// ---------------- compile-time weight-cubic table ----------------
// For span m, the 4 nonzero cubic basis weights are polynomials in u = 61x - m.
// Only 7 distinct classes (m=0,1,2 | interior | m=58,59,60). Built at compile
// time in double precision (validated R12: rel_err 3.9e-7).
namespace ct {

constexpr double knotd(int g) {
    int j = g - 3;
    if (j < 0) j = 0;
    if (j > N_SPANS) j = N_SPANS;
    return (double)j / (double)N_SPANS;
}

struct WTab { float w[7][4][4]; };   // [class][basis j][monomial k]

constexpr WTab make_wtab() {
    WTab T{};
    for (int c = 0; c < 7; c++) {
        int m = (c < 3) ? c : ((c == 3) ? 30 : c + 54);
        double f[4][4] = {};
        for (int s = 0; s < 4; s++) {
            double xs = (3.0 * m + s) / (3.0 * (double)N_SPANS);
            double l1 = xs - knotd(m + 3);
            double l2 = xs - knotd(m + 2);
            double l3 = xs - knotd(m + 1);
            double r1 = knotd(m + 4) - xs;
            double r2 = knotd(m + 5) - xs;
            double r3 = knotd(m + 6) - xs;
            double N0 = 1.0, N1 = 0.0, N2 = 0.0, N3 = 0.0, sv = 0.0, tp = 0.0;
            tp = N0 / (r1 + l1); N0 = r1 * tp; N1 = l1 * tp;
            tp = N0 / (r1 + l2); N0 = r1 * tp; sv = l2 * tp;
            tp = N1 / (r2 + l1); N1 = sv + r2 * tp; N2 = l1 * tp;
            tp = N0 / (r1 + l3); N0 = r1 * tp; sv = l3 * tp;
            tp = N1 / (r2 + l2); N1 = sv + r2 * tp; sv = l2 * tp;
            tp = N2 / (r3 + l1); N2 = sv + r3 * tp; N3 = l1 * tp;
            f[s][0] = N0; f[s][1] = N1; f[s][2] = N2; f[s][3] = N3;
        }
        for (int j = 0; j < 4; j++) {
            double f0 = f[0][j], f1 = f[1][j], f2 = f[2][j], f3 = f[3][j];
            T.w[c][j][0] = (float)f0;
            T.w[c][j][1] = (float)(-5.5 * f0 +  9.0 * f1 -  4.5 * f2 +       f3);
            T.w[c][j][2] = (float)( 9.0 * f0 - 22.5 * f1 + 18.0 * f2 - 4.5 * f3);
            T.w[c][j][3] = (float)(-4.5 * f0 + 13.5 * f1 - 13.5 * f2 + 4.5 * f3);
        }
    }
    return T;
}

}  // namespace ct

__constant__ ct::WTab g_W = ct::make_wtab();

// Branch-free shift: d[0..3] = v[r .. r+3] from v[0..7], r in {0,1,2,3}.
__device__ __forceinline__ void shift4(const float v[8], int r, float d[4]) {
    bool r2 = (r & 2) != 0;
    bool r1 = (r & 1) != 0;
    float a0 = r2 ? v[2] : v[0];
    float a1 = r2 ? v[3] : v[1];
    float a2 = r2 ? v[4] : v[2];
    float a3 = r2 ? v[5] : v[3];
    float a4 = r2 ? v[6] : v[4];
    float a5 = r2 ? v[7] : v[5];
    d[0] = r1 ? a1 : a0;
    d[1] = r1 ? a2 : a1;
    d[2] = r1 ? a3 : a2;
    d[3] = r1 ? a4 : a3;
    (void)a5;
}

__global__ void __launch_bounds__(THREADS, 8)
bspline_fused2_kernel(const float* __restrict__ x,
                      const float* __restrict__ A,
                      float* __restrict__ out) {
    __shared__ float4 Wsm[28];          // [class*4 + j] cubic coeffs
    __shared__ float  ws[THREADS / 32];

    const int row = blockIdx.x;
    const int tid = threadIdx.x;
    const int i0 = tid * 4;

    if (tid < 28) {
        const float* p = g_W.w[tid >> 2][tid & 3];
        Wsm[tid] = make_float4(p[0], p[1], p[2], p[3]);
    }

    // coalesced float4 x load
    const float4 xv = reinterpret_cast<const float4*>(x + (size_t)row * DATA_DIM)[tid];
    __syncthreads();

    // ---- phase 1: spans for all 4 dims ----
    float xs[4] = {xv.x, xv.y, xv.z, xv.w};
    int   m[4], q[4], r[4], cls[4];
    float u[4];
    #pragma unroll
    for (int d = 0; d < 4; d++) {
        float t = xs[d] * (float)N_SPANS;
        int mm = max(0, min(N_SPANS - 1, (int)t));
        m[d] = mm;
        u[d] = t - (float)mm;
        q[d] = mm >> 2;
        r[d] = mm & 3;
        cls[d] = (mm < 3) ? mm : ((mm > 57) ? mm - 54 : 3);
    }

    // ---- phase 2: issue all 8 aligned LDG.128 gathers up front ----
    const float4* A4 = reinterpret_cast<const float4*>(A);
    float v[4][8];
    #pragma unroll
    for (int d = 0; d < 4; d++) {
        int base = (i0 + d) * (BASIS_DIM / 4);
        int qa = q[d];
        int qb = min(qa + 1, BASIS_DIM / 4 - 1);   // m=60 -> r=0, weights ignore vb
        float4 va = __ldg(&A4[base + qa]);
        float4 vb = __ldg(&A4[base + qb]);
        v[d][0] = va.x; v[d][1] = va.y; v[d][2] = va.z; v[d][3] = va.w;
        v[d][4] = vb.x; v[d][5] = vb.y; v[d][6] = vb.z; v[d][7] = vb.w;
    }

    // ---- phase 3: weights (overlap with loads) + shift + dot ----
    float sum = 0.0f;
    #pragma unroll
    for (int d = 0; d < 4; d++) {
        float4 p0 = Wsm[cls[d] * 4 + 0];
        float4 p1 = Wsm[cls[d] * 4 + 1];
        float4 p2 = Wsm[cls[d] * 4 + 2];
        float4 p3 = Wsm[cls[d] * 4 + 3];
        float uu = u[d];
        float w0 = fmaf(fmaf(fmaf(p0.w, uu, p0.z), uu, p0.y), uu, p0.x);
        float w1 = fmaf(fmaf(fmaf(p1.w, uu, p1.z), uu, p1.y), uu, p1.x);
        float w2 = fmaf(fmaf(fmaf(p2.w, uu, p2.z), uu, p2.y), uu, p2.x);
        float w3 = fmaf(fmaf(fmaf(p3.w, uu, p3.z), uu, p3.y), uu, p3.x);

        float dd[4];
        shift4(v[d], r[d], dd);
        sum = fmaf(w0, dd[0], fmaf(w1, dd[1], fmaf(w2, dd[2], fmaf(w3, dd[3], sum))));
    }

    // ---- reduce + sigmoid ----
    #pragma unroll
    for (int o = 16; o > 0; o >>= 1)
        sum += __shfl_xor_sync(0xFFFFFFFFu, sum, o);

    if ((tid & 31) == 0) ws[tid >> 5] = sum;
    __syncthreads();

    if (tid == 0) {
        float s = ws[0] + ws[1] + ws[2] + ws[3];
        out[row] = 1.0f / (1.0f + __expf(-s));
    }
}

extern "C" void kernel_launch(void* const* d_in, const int* in_sizes, int n_in,
                              void* d_out, int out_size) {
    // Disambiguate by element count: x is 2048*512, A is 512*64.
    const float* x = (const float*)d_in[0];
    const float* A = (const float*)d_in[1];
    if (n_in >= 2 && in_sizes[0] == DATA_DIM * BASIS_DIM &&
        in_sizes[1] == N_ROWS * DATA_DIM) {
        x = (const float*)d_in[1];
        A = (const float*)d_in[0];
    }
    float* out = (float*)d_out;  // [2048]
    bspline_fused2_kernel<<<N_ROWS, THREADS>>>(x, A, out);
}